// round 13
// baseline (speedup 1.0000x reference)
#include <cuda_runtime.h>
#include <math.h>

#define N_NODES   100000
#define N_EDGES   1000000
#define HID       64
#define OUT_DIM   32
#define NUM_GRAPHS 512

#define SCAN_BS 1024
#define SCAN_NB ((N_NODES + SCAN_BS - 1) / SCAN_BS)   // 98

// fused gather+MLP: 64-node tile, 4 warps, warp owns 16 rows.
// dynamic smem: WT1 (64*33 u64) | WT2 (64*33 u64) | A (4 warps * 16 * 68 floats)
#define SMW_WT1 0
#define SMW_WT2 16896
#define SMW_A   33792
#define SMW_TOTAL (SMW_A + 4 * 16 * 68 * 4)   // 50688

// ---------------- device scratch -------------------------------------------
__device__ float g_h[N_NODES * HID];
__device__ float g_sums[NUM_GRAPHS * HID];
__device__ float g_Wc[HID * OUT_DIM];
__device__ float g_bc[OUT_DIM];
__device__ int   g_is64;
__device__ int   g_batch[N_NODES];
__device__ int   g_deg[N_NODES];
__device__ int   g_rowptr[N_NODES + 1];
__device__ int   g_pos[N_NODES];
__device__ int   g_csr_src[N_EDGES];
__device__ int   g_blocksum[SCAN_NB];

// ---------------- packed f32x2 helpers --------------------------------------
__device__ __forceinline__ void fma2(unsigned long long& d, unsigned long long a,
                                     unsigned long long b) {
    asm("fma.rn.f32x2 %0, %1, %2, %0;" : "+l"(d) : "l"(a), "l"(b));
}
__device__ __forceinline__ float2 unpack2(unsigned long long v) {
    float lo, hi;
    asm("mov.b64 {%0,%1}, %2;" : "=f"(lo), "=f"(hi) : "l"(v));
    return make_float2(lo, hi);
}
__device__ __forceinline__ unsigned long long pack2(float lo, float hi) {
    unsigned long long r;
    asm("mov.b64 %0, {%1,%2};" : "=l"(r) : "f"(lo), "f"(hi));
    return r;
}
__device__ __forceinline__ void red_add_f32(float* addr, float v) {
    asm volatile("red.global.add.f32 [%0], %1;" :: "l"(addr), "f"(v) : "memory");
}
__device__ __forceinline__ int load_idx(const void* buf, int i, int is64) {
    return is64 ? (int)((const long long*)buf)[i] : ((const int*)buf)[i];
}

// ---------------- setup: detect dtype + zero deg/sums + fuse head ------------
__global__ void k_setup(const int* __restrict__ ei32,
                        const float* __restrict__ Wp1, const float* __restrict__ bp1,
                        const float* __restrict__ Wp2, const float* __restrict__ bp2) {
    if (blockIdx.x == 0) {
        __shared__ int nz;
        if (threadIdx.x == 0) nz = 0;
        __syncthreads();
        if (ei32[2 * threadIdx.x + 1] != 0) nz = 1;   // benign race
        __syncthreads();
        if (threadIdx.x == 0) g_is64 = (nz == 0) ? 1 : 0;
    }
    int i = blockIdx.x * blockDim.x + threadIdx.x;
    if (i < N_NODES) g_deg[i] = 0;
    int j = i - N_NODES;
    if (j >= 0) {
        if (j < NUM_GRAPHS * HID) {
            g_sums[j] = 0.0f;
        } else if (j < NUM_GRAPHS * HID + HID * OUT_DIM) {
            int q = j - NUM_GRAPHS * HID;
            int k = q >> 5, c = q & 31;
            float s = 0.0f;
            for (int m = 0; m < HID; m++) s += Wp1[k * HID + m] * Wp2[m * OUT_DIM + c];
            g_Wc[q] = s;
        } else if (j < NUM_GRAPHS * HID + HID * OUT_DIM + OUT_DIM) {
            int c = j - NUM_GRAPHS * HID - HID * OUT_DIM;
            float s = bp2[c];
            for (int m = 0; m < HID; m++) s += bp1[m] * Wp2[m * OUT_DIM + c];
            g_bc[c] = s;
        }
    }
}

// ---------------- histogram dst degrees + repack batch -----------------------
__global__ void k_hist(const void* __restrict__ eiv, const void* __restrict__ bv) {
    int i = blockIdx.x * blockDim.x + threadIdx.x;
    int is64 = g_is64;
    if (i < N_EDGES) {
        int d = load_idx(eiv, N_EDGES + i, is64);
        atomicAdd(&g_deg[d], 1);
    }
    if (i < N_NODES) {
        g_batch[i] = load_idx(bv, i, is64);
    }
}

// ---------------- scan pass 1 -------------------------------------------------
__global__ void __launch_bounds__(SCAN_BS) k_scan_block() {
    __shared__ int sh[SCAN_BS];
    const int t = threadIdx.x;
    const int i = blockIdx.x * SCAN_BS + t;
    int v = (i < N_NODES) ? g_deg[i] : 0;
    sh[t] = v;
    __syncthreads();
    #pragma unroll
    for (int off = 1; off < SCAN_BS; off <<= 1) {
        int u = (t >= off) ? sh[t - off] : 0;
        __syncthreads();
        sh[t] += u;
        __syncthreads();
    }
    if (i < N_NODES) g_rowptr[i] = sh[t] - v;
    if (t == SCAN_BS - 1) g_blocksum[blockIdx.x] = sh[t];
}

// ---------------- scan pass 2 -------------------------------------------------
__global__ void __launch_bounds__(256) k_scan_add() {
    __shared__ int sh[128];
    const int t = threadIdx.x;
    if (t < 128) sh[t] = (t < SCAN_NB) ? g_blocksum[t] : 0;
    __syncthreads();
    #pragma unroll
    for (int off = 1; off < 128; off <<= 1) {
        int v = (t < 128 && t >= off) ? sh[t - off] : 0;
        __syncthreads();
        if (t < 128) sh[t] += v;
        __syncthreads();
    }
    int chunk = blockIdx.x >> 2;
    int boff = (chunk == 0) ? 0 : sh[chunk - 1];
    int i = blockIdx.x * 256 + t;
    if (i < N_NODES) {
        int v = g_rowptr[i] + boff;
        g_rowptr[i] = v;
        g_pos[i] = v;
    }
    if (blockIdx.x == 0 && t == 0) g_rowptr[N_NODES] = sh[SCAN_NB - 1];
}

// ---------------- fill CSR ------------------------------------------------------
__global__ void k_fill(const void* __restrict__ eiv) {
    int e = blockIdx.x * blockDim.x + threadIdx.x;
    if (e >= N_EDGES) return;
    int is64 = g_is64;
    int s = load_idx(eiv, e, is64);
    int d = load_idx(eiv, N_EDGES + e, is64);
    int p = atomicAdd(&g_pos[d], 1);
    g_csr_src[p] = s;
}

// ---------------- fused warp-private gather + GIN MLP -------------------------
// 128 threads, 64-node tile; warp owns 16 rows (warp-private A buffer).
// Weights staged once per block (sole __syncthreads); after that warps are
// independent: gather own rows -> GEMM1 -> relu -> GEMM2 -> epilogue.
// MODE 0: relu -> g_h.   MODE 1: raw -> emb_out, relu red -> g_sums.
template <int MODE>
__global__ void __launch_bounds__(128) k_gmlp(
    const float* __restrict__ feat_in,   // x (MODE 0); MODE 1 uses g_h
    const float* __restrict__ W1, const float* __restrict__ b1,
    const float* __restrict__ W2, const float* __restrict__ b2,
    float* __restrict__ emb_out)
{
    extern __shared__ char sm[];
    unsigned long long* WT1 = reinterpret_cast<unsigned long long*>(sm + SMW_WT1);
    unsigned long long* WT2 = reinterpret_cast<unsigned long long*>(sm + SMW_WT2);
    float* Abase             = reinterpret_cast<float*>(sm + SMW_A);

    const int t = threadIdx.x;
    const int warp = t >> 5;
    const int lane = t & 31;
    const int half = lane >> 4;        // 0/1: row sub-group
    const int c = lane & 15;           // column lane
    const int base = blockIdx.x * 64;
    const float* feat = (MODE == 0) ? feat_in : g_h;

    // ---- stage both weight tiles (packed even/odd k pairs, transposed) ----
    #pragma unroll
    for (int it = 0; it < 16; it++) {
        int idx = t + 128 * it;                  // 2048 = 64 cols x 32 k2
        int cc = idx & 63, k2 = idx >> 6;
        WT1[cc * 33 + k2] = pack2(__ldg(W1 + (2 * k2) * HID + cc),
                                  __ldg(W1 + (2 * k2 + 1) * HID + cc));
        WT2[cc * 33 + k2] = pack2(__ldg(W2 + (2 * k2) * HID + cc),
                                  __ldg(W2 + (2 * k2 + 1) * HID + cc));
    }
    __syncthreads();   // only block-wide barrier

    // ---- warp-private gather of 16 rows (2 rows per pass, half-warp each) ----
    float* A = Abase + warp * (16 * 68);
    #pragma unroll 2
    for (int pass = 0; pass < 8; pass++) {
        int rl = pass * 2 + half;
        int node = base + warp * 16 + rl;
        float4 acc = make_float4(0.f, 0.f, 0.f, 0.f);
        if (node < N_NODES) {
            acc = __ldg(reinterpret_cast<const float4*>(feat + (size_t)node * HID) + c);
            int p  = __ldg(&g_rowptr[node]);
            int pe = __ldg(&g_rowptr[node + 1]);
            for (; p + 1 < pe; p += 2) {
                int s0 = __ldg(&g_csr_src[p]);
                int s1 = __ldg(&g_csr_src[p + 1]);
                float4 v0 = __ldg(reinterpret_cast<const float4*>(feat + (size_t)s0 * HID) + c);
                float4 v1 = __ldg(reinterpret_cast<const float4*>(feat + (size_t)s1 * HID) + c);
                acc.x += v0.x + v1.x; acc.y += v0.y + v1.y;
                acc.z += v0.z + v1.z; acc.w += v0.w + v1.w;
            }
            if (p < pe) {
                int s0 = __ldg(&g_csr_src[p]);
                float4 v0 = __ldg(reinterpret_cast<const float4*>(feat + (size_t)s0 * HID) + c);
                acc.x += v0.x; acc.y += v0.y; acc.z += v0.z; acc.w += v0.w;
            }
        }
        float* pA = A + rl * 68 + c * 4;
        pA[0] = acc.x; pA[1] = acc.y; pA[2] = acc.z; pA[3] = acc.w;
    }
    __syncwarp();

    unsigned long long acc2[8][4];
    #pragma unroll
    for (int r = 0; r < 8; r++)
        #pragma unroll
        for (int j = 0; j < 4; j++) acc2[r][j] = 0ULL;

    // ---- GEMM phase 1: rows half*8..+7, cols c+16j ----
    #pragma unroll 4
    for (int k2 = 0; k2 < 32; k2++) {
        unsigned long long w0 = WT1[(c +  0) * 33 + k2];
        unsigned long long w1 = WT1[(c + 16) * 33 + k2];
        unsigned long long w2 = WT1[(c + 32) * 33 + k2];
        unsigned long long w3 = WT1[(c + 48) * 33 + k2];
        #pragma unroll
        for (int r = 0; r < 8; r++) {
            unsigned long long a2 =
                *reinterpret_cast<const unsigned long long*>(A + (half * 8 + r) * 68 + 2 * k2);
            fma2(acc2[r][0], a2, w0);
            fma2(acc2[r][1], a2, w1);
            fma2(acc2[r][2], a2, w2);
            fma2(acc2[r][3], a2, w3);
        }
    }

    float bias[4];
    #pragma unroll
    for (int j = 0; j < 4; j++) bias[j] = __ldg(b1 + c + 16 * j);

    __syncwarp();   // phase-1 A reads complete before overwrite

    #pragma unroll
    for (int r = 0; r < 8; r++) {
        #pragma unroll
        for (int j = 0; j < 4; j++) {
            float2 p = unpack2(acc2[r][j]);
            A[(half * 8 + r) * 68 + c + 16 * j] = fmaxf(p.x + p.y + bias[j], 0.0f);
            acc2[r][j] = 0ULL;
        }
    }
    __syncwarp();   // hidden tile complete

    // ---- GEMM phase 2 ----
    #pragma unroll 4
    for (int k2 = 0; k2 < 32; k2++) {
        unsigned long long w0 = WT2[(c +  0) * 33 + k2];
        unsigned long long w1 = WT2[(c + 16) * 33 + k2];
        unsigned long long w2 = WT2[(c + 32) * 33 + k2];
        unsigned long long w3 = WT2[(c + 48) * 33 + k2];
        #pragma unroll
        for (int r = 0; r < 8; r++) {
            unsigned long long a2 =
                *reinterpret_cast<const unsigned long long*>(A + (half * 8 + r) * 68 + 2 * k2);
            fma2(acc2[r][0], a2, w0);
            fma2(acc2[r][1], a2, w1);
            fma2(acc2[r][2], a2, w2);
            fma2(acc2[r][3], a2, w3);
        }
    }

    #pragma unroll
    for (int j = 0; j < 4; j++) bias[j] = __ldg(b2 + c + 16 * j);

    // ---- epilogue ----
    #pragma unroll
    for (int r = 0; r < 8; r++) {
        int node = base + warp * 16 + half * 8 + r;
        if (node >= N_NODES) continue;
        if (MODE == 0) {
            float* dst = g_h + (size_t)node * HID;
            #pragma unroll
            for (int j = 0; j < 4; j++) {
                float2 p = unpack2(acc2[r][j]);
                dst[c + 16 * j] = fmaxf(p.x + p.y + bias[j], 0.0f);
            }
        } else {
            float* dst = emb_out + (size_t)node * HID;
            int gidx = g_batch[node];
            float* sums = g_sums + (size_t)gidx * HID;
            #pragma unroll
            for (int j = 0; j < 4; j++) {
                float2 p = unpack2(acc2[r][j]);
                float v = p.x + p.y + bias[j];
                dst[c + 16 * j] = v;
                red_add_f32(sums + c + 16 * j, fmaxf(v, 0.0f));
            }
        }
    }
}

// ---------------- final head -----------------------------------------------------
__global__ void k_final(float* __restrict__ outp) {
    int g = blockIdx.x * blockDim.x + threadIdx.x;
    if (g >= NUM_GRAPHS) return;
    int l0, l1;
    {
        int v = g;
        int a = 0, b = N_NODES;
        while (a < b) { int m = (a + b) >> 1; if (g_batch[m] < v) a = m + 1; else b = m; }
        l0 = a;
        v = g + 1; a = l0; b = N_NODES;
        while (a < b) { int m = (a + b) >> 1; if (g_batch[m] < v) a = m + 1; else b = m; }
        l1 = a;
    }
    float cnt = (float)(l1 - l0);
    float inv = 1.0f / fmaxf(cnt, 1.0f);

    float acc[OUT_DIM];
    #pragma unroll
    for (int c = 0; c < OUT_DIM; c++) acc[c] = g_bc[c];
    for (int k = 0; k < HID; k++) {
        float p = g_sums[g * HID + k] * inv;
        #pragma unroll
        for (int c = 0; c < OUT_DIM; c++) acc[c] += p * g_Wc[k * OUT_DIM + c];
    }
    float m = acc[0];
    #pragma unroll
    for (int c = 1; c < OUT_DIM; c++) m = fmaxf(m, acc[c]);
    float s = 0.0f;
    #pragma unroll
    for (int c = 0; c < OUT_DIM; c++) s += expf(acc[c] - m);
    float ls = logf(s) + m;
    #pragma unroll
    for (int c = 0; c < OUT_DIM; c++) outp[g * OUT_DIM + c] = acc[c] - ls;
}

// ---------------- host launch ------------------------------------------------------
extern "C" void kernel_launch(void* const* d_in, const int* in_sizes, int n_in,
                              void* d_out, int out_size) {
    const float* x     = (const float*)d_in[0];
    const void*  ei    = d_in[1];
    const void*  batch = d_in[2];
    const float* W1a = (const float*)d_in[3];
    const float* b1a = (const float*)d_in[4];
    const float* W2a = (const float*)d_in[5];
    const float* b2a = (const float*)d_in[6];
    const float* W1b = (const float*)d_in[7];
    const float* b1b = (const float*)d_in[8];
    const float* W2b = (const float*)d_in[9];
    const float* b2b = (const float*)d_in[10];
    const float* Wp1 = (const float*)d_in[11];
    const float* bp1 = (const float*)d_in[12];
    const float* Wp2 = (const float*)d_in[13];
    const float* bp2 = (const float*)d_in[14];

    float* out     = (float*)d_out;
    float* emb_out = out;
    float* lsm_out = out + (size_t)N_NODES * HID;

    const int mlp_blocks = (N_NODES + 63) / 64;
    const int setup_n    = N_NODES + NUM_GRAPHS * HID + HID * OUT_DIM + OUT_DIM;

    cudaFuncSetAttribute(k_gmlp<0>, cudaFuncAttributeMaxDynamicSharedMemorySize, SMW_TOTAL);
    cudaFuncSetAttribute(k_gmlp<1>, cudaFuncAttributeMaxDynamicSharedMemorySize, SMW_TOTAL);

    k_setup<<<(setup_n + 255) / 256, 256>>>((const int*)ei, Wp1, bp1, Wp2, bp2);
    k_hist<<<(N_EDGES + 255) / 256, 256>>>(ei, batch);
    k_scan_block<<<SCAN_NB, SCAN_BS>>>();
    k_scan_add<<<(N_NODES + 255) / 256, 256>>>();
    k_fill<<<(N_EDGES + 255) / 256, 256>>>(ei);

    // layer 0 (gather from x) + layer 1 (gather from g_h), fused gather+MLP
    k_gmlp<0><<<mlp_blocks, 128, SMW_TOTAL>>>(x, W1a, b1a, W2a, b2a, nullptr);
    k_gmlp<1><<<mlp_blocks, 128, SMW_TOTAL>>>(nullptr, W1b, b1b, W2b, b2b, emb_out);

    k_final<<<(NUM_GRAPHS + 127) / 128, 128>>>(lsm_out);
}

// round 14
// speedup vs baseline: 1.2649x; 1.2649x over previous
#include <cuda_runtime.h>
#include <math.h>

#define N_NODES   100000
#define N_EDGES   1000000
#define HID       64
#define OUT_DIM   32
#define NUM_GRAPHS 512

#define SCAN_BS 1024
#define SCAN_NB ((N_NODES + SCAN_BS - 1) / SCAN_BS)   // 98

// ---------------- device scratch -------------------------------------------
__device__ float g_agg[N_NODES * HID];
__device__ float g_h[N_NODES * HID];
__device__ float g_sums[NUM_GRAPHS * HID];
__device__ float g_Wc[HID * OUT_DIM];
__device__ float g_bc[OUT_DIM];
__device__ int   g_is64;
__device__ int   g_batch[N_NODES];
__device__ int   g_deg[N_NODES];
__device__ int   g_rowptr[N_NODES + 1];
__device__ int   g_pos[N_NODES];
__device__ int   g_csr_src[N_EDGES];
__device__ int   g_blocksum[SCAN_NB];

// ---------------- packed f32x2 helpers --------------------------------------
__device__ __forceinline__ void fma2(unsigned long long& d, unsigned long long a,
                                     unsigned long long b) {
    asm("fma.rn.f32x2 %0, %1, %2, %0;" : "+l"(d) : "l"(a), "l"(b));
}
__device__ __forceinline__ float2 unpack2(unsigned long long v) {
    float lo, hi;
    asm("mov.b64 {%0,%1}, %2;" : "=f"(lo), "=f"(hi) : "l"(v));
    return make_float2(lo, hi);
}
__device__ __forceinline__ unsigned long long pack2(float lo, float hi) {
    unsigned long long r;
    asm("mov.b64 %0, {%1,%2};" : "=l"(r) : "f"(lo), "f"(hi));
    return r;
}
__device__ __forceinline__ void red_add_f32(float* addr, float v) {
    asm volatile("red.global.add.f32 [%0], %1;" :: "l"(addr), "f"(v) : "memory");
}
__device__ __forceinline__ int load_idx(const void* buf, int i, int is64) {
    return is64 ? (int)((const long long*)buf)[i] : ((const int*)buf)[i];
}

// ---------------- setup: detect dtype + zero deg/sums + fuse head ------------
__global__ void k_setup(const int* __restrict__ ei32,
                        const float* __restrict__ Wp1, const float* __restrict__ bp1,
                        const float* __restrict__ Wp2, const float* __restrict__ bp2) {
    if (blockIdx.x == 0) {
        __shared__ int nz;
        if (threadIdx.x == 0) nz = 0;
        __syncthreads();
        if (ei32[2 * threadIdx.x + 1] != 0) nz = 1;   // benign race
        __syncthreads();
        if (threadIdx.x == 0) g_is64 = (nz == 0) ? 1 : 0;
    }
    int i = blockIdx.x * blockDim.x + threadIdx.x;
    if (i < N_NODES) g_deg[i] = 0;
    int j = i - N_NODES;
    if (j >= 0) {
        if (j < NUM_GRAPHS * HID) {
            g_sums[j] = 0.0f;
        } else if (j < NUM_GRAPHS * HID + HID * OUT_DIM) {
            int q = j - NUM_GRAPHS * HID;
            int k = q >> 5, c = q & 31;
            float s = 0.0f;
            for (int m = 0; m < HID; m++) s += Wp1[k * HID + m] * Wp2[m * OUT_DIM + c];
            g_Wc[q] = s;
        } else if (j < NUM_GRAPHS * HID + HID * OUT_DIM + OUT_DIM) {
            int c = j - NUM_GRAPHS * HID - HID * OUT_DIM;
            float s = bp2[c];
            for (int m = 0; m < HID; m++) s += bp1[m] * Wp2[m * OUT_DIM + c];
            g_bc[c] = s;
        }
    }
}

// ---------------- histogram dst degrees (2 edges/thread) + batch repack ------
__global__ void k_hist(const void* __restrict__ eiv, const void* __restrict__ bv) {
    int i = blockIdx.x * blockDim.x + threadIdx.x;
    int is64 = g_is64;
    int e = i * 2;
    if (e < N_EDGES) {
        int d0, d1 = -1;
        if (is64) {
            longlong2 dd = __ldg(reinterpret_cast<const longlong2*>(
                                  (const long long*)eiv + N_EDGES + e));
            d0 = (int)dd.x;
            if (e + 1 < N_EDGES) d1 = (int)dd.y;
        } else {
            int2 dd = __ldg(reinterpret_cast<const int2*>((const int*)eiv + N_EDGES + e));
            d0 = dd.x;
            if (e + 1 < N_EDGES) d1 = dd.y;
        }
        atomicAdd(&g_deg[d0], 1);
        if (d1 >= 0) atomicAdd(&g_deg[d1], 1);
    }
    if (i < N_NODES) {
        g_batch[i] = load_idx(bv, i, is64);
    }
}

// ---------------- scan pass 1: block-local exclusive scan --------------------
__global__ void __launch_bounds__(SCAN_BS) k_scan_block() {
    __shared__ int sh[SCAN_BS];
    const int t = threadIdx.x;
    const int i = blockIdx.x * SCAN_BS + t;
    int v = (i < N_NODES) ? g_deg[i] : 0;
    sh[t] = v;
    __syncthreads();
    #pragma unroll
    for (int off = 1; off < SCAN_BS; off <<= 1) {
        int u = (t >= off) ? sh[t - off] : 0;
        __syncthreads();
        sh[t] += u;
        __syncthreads();
    }
    if (i < N_NODES) g_rowptr[i] = sh[t] - v;
    if (t == SCAN_BS - 1) g_blocksum[blockIdx.x] = sh[t];
}

// ---------------- scan pass 2: per-block redundant top scan + add ------------
__global__ void __launch_bounds__(256) k_scan_add() {
    __shared__ int sh[128];
    const int t = threadIdx.x;
    if (t < 128) sh[t] = (t < SCAN_NB) ? g_blocksum[t] : 0;
    __syncthreads();
    #pragma unroll
    for (int off = 1; off < 128; off <<= 1) {
        int v = (t < 128 && t >= off) ? sh[t - off] : 0;
        __syncthreads();
        if (t < 128) sh[t] += v;
        __syncthreads();
    }
    int chunk = blockIdx.x >> 2;                 // 256-thread block -> 1024-chunk id
    int boff = (chunk == 0) ? 0 : sh[chunk - 1];
    int i = blockIdx.x * 256 + t;
    if (i < N_NODES) {
        int v = g_rowptr[i] + boff;
        g_rowptr[i] = v;
        g_pos[i] = v;
    }
    if (blockIdx.x == 0 && t == 0) g_rowptr[N_NODES] = sh[SCAN_NB - 1];
}

// ---------------- fill CSR (2 edges/thread, vectorized loads) ----------------
__global__ void k_fill(const void* __restrict__ eiv) {
    int i = blockIdx.x * blockDim.x + threadIdx.x;
    int e = i * 2;
    if (e >= N_EDGES) return;
    int is64 = g_is64;
    int s0, d0, s1 = -1, d1 = -1;
    if (is64) {
        longlong2 ss = __ldg(reinterpret_cast<const longlong2*>((const long long*)eiv + e));
        longlong2 dd = __ldg(reinterpret_cast<const longlong2*>(
                              (const long long*)eiv + N_EDGES + e));
        s0 = (int)ss.x; d0 = (int)dd.x;
        if (e + 1 < N_EDGES) { s1 = (int)ss.y; d1 = (int)dd.y; }
    } else {
        int2 ss = __ldg(reinterpret_cast<const int2*>((const int*)eiv + e));
        int2 dd = __ldg(reinterpret_cast<const int2*>((const int*)eiv + N_EDGES + e));
        s0 = ss.x; d0 = dd.x;
        if (e + 1 < N_EDGES) { s1 = ss.y; d1 = dd.y; }
    }
    int p0 = atomicAdd(&g_pos[d0], 1);
    g_csr_src[p0] = s0;
    if (d1 >= 0) {
        int p1 = atomicAdd(&g_pos[d1], 1);
        g_csr_src[p1] = s1;
    }
}

// ---------------- gather: agg[n] = self[n] + sum_{j->n} feat[j] ---------------
// 16 threads/node, float4 each; 2 edges in flight to break the L2-latency chain.
template <bool USE_H>
__global__ void k_gather(const float* __restrict__ x) {
    int idx = blockIdx.x * blockDim.x + threadIdx.x;
    if (idx >= N_NODES * 16) return;
    int node = idx >> 4;
    int c = idx & 15;
    const float* feat = USE_H ? g_h : x;

    float4 acc = __ldg(reinterpret_cast<const float4*>(feat + (size_t)node * HID) + c);
    int p  = g_rowptr[node];
    int pe = g_rowptr[node + 1];
    for (; p + 1 < pe; p += 2) {
        int s0 = __ldg(&g_csr_src[p]);
        int s1 = __ldg(&g_csr_src[p + 1]);
        float4 v0 = __ldg(reinterpret_cast<const float4*>(feat + (size_t)s0 * HID) + c);
        float4 v1 = __ldg(reinterpret_cast<const float4*>(feat + (size_t)s1 * HID) + c);
        acc.x += v0.x + v1.x; acc.y += v0.y + v1.y;
        acc.z += v0.z + v1.z; acc.w += v0.w + v1.w;
    }
    if (p < pe) {
        int s0 = __ldg(&g_csr_src[p]);
        float4 v0 = __ldg(reinterpret_cast<const float4*>(feat + (size_t)s0 * HID) + c);
        acc.x += v0.x; acc.y += v0.y; acc.z += v0.z; acc.w += v0.w;
    }
    *(reinterpret_cast<float4*>(g_agg + (size_t)node * HID) + c) = acc;
}

// ---------------- fused GIN MLP with packed f32x2 FMA -------------------------
template <int MODE>
__global__ void __launch_bounds__(128) k_mlp(
    const float* __restrict__ W1, const float* __restrict__ b1,
    const float* __restrict__ W2, const float* __restrict__ b2,
    float* __restrict__ emb_out)
{
    __shared__ __align__(16) float A[64 * 66];
    __shared__ __align__(16) unsigned long long WT[64 * 33];
    const int t = threadIdx.x;
    const int base = blockIdx.x * 64;
    const int cg = t & 15;
    const int ng = t >> 4;

    #pragma unroll
    for (int it = 0; it < 8; it++) {
        int L4 = t + 128 * it;
        int row = L4 >> 4, c4 = L4 & 15;
        int node = base + row;
        float4 v = make_float4(0.f, 0.f, 0.f, 0.f);
        if (node < N_NODES)
            v = __ldg(reinterpret_cast<const float4*>(g_agg + (size_t)node * HID) + c4);
        float* p = A + row * 66 + c4 * 4;
        p[0] = v.x; p[1] = v.y; p[2] = v.z; p[3] = v.w;
    }
    #pragma unroll
    for (int it = 0; it < 16; it++) {
        int idx = t + 128 * it;
        int c = idx & 63, k2 = idx >> 6;
        float w0 = __ldg(W1 + (2 * k2) * HID + c);
        float w1 = __ldg(W1 + (2 * k2 + 1) * HID + c);
        WT[c * 33 + k2] = pack2(w0, w1);
    }
    __syncthreads();

    unsigned long long acc2[8][4];
    #pragma unroll
    for (int r = 0; r < 8; r++)
        #pragma unroll
        for (int j = 0; j < 4; j++) acc2[r][j] = 0ULL;

    #pragma unroll 4
    for (int k2 = 0; k2 < 32; k2++) {
        unsigned long long w0 = WT[(cg +  0) * 33 + k2];
        unsigned long long w1 = WT[(cg + 16) * 33 + k2];
        unsigned long long w2 = WT[(cg + 32) * 33 + k2];
        unsigned long long w3 = WT[(cg + 48) * 33 + k2];
        #pragma unroll
        for (int r = 0; r < 8; r++) {
            unsigned long long a2 =
                *reinterpret_cast<const unsigned long long*>(A + (ng * 8 + r) * 66 + 2 * k2);
            fma2(acc2[r][0], a2, w0);
            fma2(acc2[r][1], a2, w1);
            fma2(acc2[r][2], a2, w2);
            fma2(acc2[r][3], a2, w3);
        }
    }

    float bias[4];
    #pragma unroll
    for (int j = 0; j < 4; j++) bias[j] = __ldg(b1 + cg + 16 * j);

    __syncthreads();

    #pragma unroll
    for (int r = 0; r < 8; r++) {
        #pragma unroll
        for (int j = 0; j < 4; j++) {
            float2 p = unpack2(acc2[r][j]);
            A[(ng * 8 + r) * 66 + cg + 16 * j] = fmaxf(p.x + p.y + bias[j], 0.0f);
            acc2[r][j] = 0ULL;
        }
    }
    #pragma unroll
    for (int it = 0; it < 16; it++) {
        int idx = t + 128 * it;
        int c = idx & 63, k2 = idx >> 6;
        float w0 = __ldg(W2 + (2 * k2) * HID + c);
        float w1 = __ldg(W2 + (2 * k2 + 1) * HID + c);
        WT[c * 33 + k2] = pack2(w0, w1);
    }
    __syncthreads();

    #pragma unroll 4
    for (int k2 = 0; k2 < 32; k2++) {
        unsigned long long w0 = WT[(cg +  0) * 33 + k2];
        unsigned long long w1 = WT[(cg + 16) * 33 + k2];
        unsigned long long w2 = WT[(cg + 32) * 33 + k2];
        unsigned long long w3 = WT[(cg + 48) * 33 + k2];
        #pragma unroll
        for (int r = 0; r < 8; r++) {
            unsigned long long a2 =
                *reinterpret_cast<const unsigned long long*>(A + (ng * 8 + r) * 66 + 2 * k2);
            fma2(acc2[r][0], a2, w0);
            fma2(acc2[r][1], a2, w1);
            fma2(acc2[r][2], a2, w2);
            fma2(acc2[r][3], a2, w3);
        }
    }

    #pragma unroll
    for (int j = 0; j < 4; j++) bias[j] = __ldg(b2 + cg + 16 * j);

    #pragma unroll
    for (int r = 0; r < 8; r++) {
        int node = base + ng * 8 + r;
        if (node >= N_NODES) continue;
        if (MODE == 0) {
            #pragma unroll
            for (int j = 0; j < 4; j++) {
                float2 p = unpack2(acc2[r][j]);
                float v = fmaxf(p.x + p.y + bias[j], 0.0f);
                g_h[(size_t)node * HID + cg + 16 * j] = v;
            }
        } else {
            int gidx = g_batch[node];
            #pragma unroll
            for (int j = 0; j < 4; j++) {
                float2 p = unpack2(acc2[r][j]);
                float v = p.x + p.y + bias[j];
                int col = cg + 16 * j;
                emb_out[(size_t)node * HID + col] = v;
                red_add_f32(g_sums + (size_t)gidx * HID + col, fmaxf(v, 0.0f));
            }
        }
    }
}

// ---------------- final head ---------------------------------------------------
__global__ void k_final(float* __restrict__ outp) {
    int g = blockIdx.x * blockDim.x + threadIdx.x;
    if (g >= NUM_GRAPHS) return;
    int l0, l1;
    {
        int v = g;
        int a = 0, b = N_NODES;
        while (a < b) { int m = (a + b) >> 1; if (g_batch[m] < v) a = m + 1; else b = m; }
        l0 = a;
        v = g + 1; a = l0; b = N_NODES;
        while (a < b) { int m = (a + b) >> 1; if (g_batch[m] < v) a = m + 1; else b = m; }
        l1 = a;
    }
    float cnt = (float)(l1 - l0);
    float inv = 1.0f / fmaxf(cnt, 1.0f);

    float acc[OUT_DIM];
    #pragma unroll
    for (int c = 0; c < OUT_DIM; c++) acc[c] = g_bc[c];
    for (int k = 0; k < HID; k++) {
        float p = g_sums[g * HID + k] * inv;
        #pragma unroll
        for (int c = 0; c < OUT_DIM; c++) acc[c] += p * g_Wc[k * OUT_DIM + c];
    }
    float m = acc[0];
    #pragma unroll
    for (int c = 1; c < OUT_DIM; c++) m = fmaxf(m, acc[c]);
    float s = 0.0f;
    #pragma unroll
    for (int c = 0; c < OUT_DIM; c++) s += expf(acc[c] - m);
    float ls = logf(s) + m;
    #pragma unroll
    for (int c = 0; c < OUT_DIM; c++) outp[g * OUT_DIM + c] = acc[c] - ls;
}

// ---------------- host launch ----------------------------------------------------
extern "C" void kernel_launch(void* const* d_in, const int* in_sizes, int n_in,
                              void* d_out, int out_size) {
    const float* x     = (const float*)d_in[0];
    const void*  ei    = d_in[1];
    const void*  batch = d_in[2];
    const float* W1a = (const float*)d_in[3];
    const float* b1a = (const float*)d_in[4];
    const float* W2a = (const float*)d_in[5];
    const float* b2a = (const float*)d_in[6];
    const float* W1b = (const float*)d_in[7];
    const float* b1b = (const float*)d_in[8];
    const float* W2b = (const float*)d_in[9];
    const float* b2b = (const float*)d_in[10];
    const float* Wp1 = (const float*)d_in[11];
    const float* bp1 = (const float*)d_in[12];
    const float* Wp2 = (const float*)d_in[13];
    const float* bp2 = (const float*)d_in[14];

    float* out     = (float*)d_out;
    float* emb_out = out;
    float* lsm_out = out + (size_t)N_NODES * HID;

    const int mlp_blocks    = (N_NODES + 63) / 64;
    const int gather_blocks = (N_NODES * 16 + 255) / 256;
    const int setup_n       = N_NODES + NUM_GRAPHS * HID + HID * OUT_DIM + OUT_DIM;
    const int half_edges    = (N_EDGES + 1) / 2;
    // k_hist covers max(half_edges threads for edges, N_NODES for batch repack)
    const int hist_n        = (half_edges > N_NODES) ? half_edges : N_NODES;

    k_setup<<<(setup_n + 255) / 256, 256>>>((const int*)ei, Wp1, bp1, Wp2, bp2);
    k_hist<<<(hist_n + 255) / 256, 256>>>(ei, batch);
    k_scan_block<<<SCAN_NB, SCAN_BS>>>();
    k_scan_add<<<(N_NODES + 255) / 256, 256>>>();
    k_fill<<<(half_edges + 255) / 256, 256>>>(ei);

    // layer 0
    k_gather<false><<<gather_blocks, 256>>>(x);
    k_mlp<0><<<mlp_blocks, 128>>>(W1a, b1a, W2a, b2a, nullptr);

    // layer 1
    k_gather<true><<<gather_blocks, 256>>>(x);
    k_mlp<1><<<mlp_blocks, 128>>>(W1b, b1b, W2b, b2b, emb_out);

    k_final<<<(NUM_GRAPHS + 127) / 128, 128>>>(lsm_out);
}